// round 14
// baseline (speedup 1.0000x reference)
#include <cuda_runtime.h>
#include <cuda_fp16.h>
#include <cstdint>
#include <math.h>

#define B_ 32
#define D_ 768
#define L_ 12
#define HEADS_ 12
#define DH_ 64
#define MLP_ 3072
#define NC_ 1000
#define N_ 197
#define NP_ 196
#define NPAD 256
#define MTOK (B_*N_)       // 6304
#define MPATCH (B_*NP_)    // 6272

// ---------------- scratch (device globals; no runtime allocation) ----------
__device__ float  g_x  [MTOK*D_];                         // residual stream fp32
__device__ __half g_h  [MTOK*D_];
__device__ __half g_q  [MTOK*D_];
__device__ __half g_k  [MTOK*D_];
__device__ __half g_o  [MTOK*D_];
__device__ __half g_mlp[(long long)MTOK*MLP_];
__device__ __half g_sc [(long long)B_*HEADS_*N_*NPAD];    // probs, ld=256
__device__ __half g_vt [(long long)B_*HEADS_*DH_*NPAD];   // V^T per head, ld=256
__device__ __half g_col[(long long)MPATCH*768];
__device__ float  g_po [(long long)MPATCH*D_];
__device__ float  g_pool[B_*D_];
__device__ __half g_pln [B_*D_];
__device__ __half g_pwr[(long long)D_*768];               // patch_w as half
// transposed (half) weights, [N,K] K-major
__device__ __half g_wqkvt[(long long)L_*3*D_*D_];         // stacked q|k|v, 2304 x 768
__device__ float  g_bqkv [(long long)L_*3*D_];            // stacked biases (fp32)
__device__ __half g_wot[(long long)L_*D_*D_];
__device__ __half g_w1t[(long long)L_*D_*MLP_];
__device__ __half g_w2t[(long long)L_*D_*MLP_];
__device__ __half g_hwt[(long long)NC_*D_];

__device__ __forceinline__ float gelu_f(float x) {
    float x3 = x*x*x;
    return 0.5f*x*(1.0f + tanhf(0.7978845608028654f*(x + 0.044715f*x3)));
}

// ---------------- PTX helpers ----------------------------------------------
__device__ __forceinline__ uint32_t smem_u32(const void* p){
    uint32_t a;
    asm("{ .reg .u64 t; cvta.to.shared.u64 t, %1; cvt.u32.u64 %0, t; }" : "=r"(a) : "l"(p));
    return a;
}
__device__ __forceinline__ void cp16(uint32_t dst, const void* src, int srcbytes){
    asm volatile("cp.async.cg.shared.global [%0], [%1], 16, %2;"
                 :: "r"(dst), "l"(src), "r"(srcbytes));
}
#define CP_COMMIT() asm volatile("cp.async.commit_group;" ::: "memory")
template<int Nw> __device__ __forceinline__ void cp_wait(){
    asm volatile("cp.async.wait_group %0;" :: "n"(Nw) : "memory");
}
// fp16 mma: D += A*B, m16n8k16, fp32 accumulate
__device__ __forceinline__ void mma16(float* d, const uint32_t* a, uint32_t b0, uint32_t b1){
    asm volatile("mma.sync.aligned.m16n8k16.row.col.f32.f16.f16.f32 "
        "{%0,%1,%2,%3}, {%4,%5,%6,%7}, {%8,%9}, {%0,%1,%2,%3};"
        : "+f"(d[0]), "+f"(d[1]), "+f"(d[2]), "+f"(d[3])
        : "r"(a[0]), "r"(a[1]), "r"(a[2]), "r"(a[3]), "r"(b0), "r"(b1));
}
__device__ __forceinline__ void ldsm4(uint32_t& r0, uint32_t& r1, uint32_t& r2, uint32_t& r3,
                                      uint32_t addr){
    asm volatile("ldmatrix.sync.aligned.m8n8.x4.shared.b16 {%0,%1,%2,%3}, [%4];"
        : "=r"(r0), "=r"(r1), "=r"(r2), "=r"(r3) : "r"(addr));
}
#define SWZ128(o) ((o) ^ (((o) >> 3) & 0x70))

// ---------------- mma.sync fp16 batched GEMM --------------------------------
// C[M,N] = A[M,K] @ B[N,K]^T  (both half, K-major). K must be a multiple of 64.
// BK = 64 halves = one 128B SW128 atom per row. Fragments loaded via
// ldmatrix.x4 with per-lane swizzle constant lx; A and B consume the identical
// chunk permutation (ks, ks+4) -> exact. Register ping-pong on fragments.
// BM in {64,128}: warp grid is (BM/32) x (8/(BM/32)). OCC = min CTAs/SM.
// EPI: 0 bias, 1 bias+gelu, 2 bias+residual(float out),
//      4 fused-QKV routing (seg0->C, seg1->C2 half; seg2->C3 transposed-V half),
//      5 fused softmax (scores -> probs half, scale 0.125, valid cols < 197)
// RND=true: output is __half; RND=false: output is float (EPI 4,5 always half).
template<int BM, int BN, int EPI, bool RND, int OCC>
__global__ void __launch_bounds__(256, OCC)
tgemm(const __half* __restrict__ A, const __half* __restrict__ Bm,
      const float* __restrict__ bias, const float* __restrict__ Res,
      void* __restrict__ C, void* __restrict__ C2, void* __restrict__ C3,
      int M, int Nn, int K, int lda, int ldb, int ldc, int zdiv,
      long long sA1, long long sA2, long long sB1, long long sB2,
      long long sC1, long long sC2)
{
    constexpr int BK = 64, S = 3;
    constexpr int ABYT = BM * 128;                 // bytes per A stage
    constexpr int BBYT = BN * 128;
    constexpr int STGB = ABYT + BBYT;
    constexpr int WROWS = BM / 32;                 // warps along M
    constexpr int WCOLS = 8 / WROWS;               // warps along N
    constexpr int WN  = BN / WCOLS;                // warp tile N
    constexpr int NT  = WN / 8;
    constexpr int NP2 = NT / 2;

    extern __shared__ float smf[];
    uint32_t sb = smem_u32(smf);
    int tid = threadIdx.x, lane = tid & 31, wid = tid >> 5;
    int wm = wid % WROWS, wn = wid / WROWS;

    int rowBase = blockIdx.y * BM;
    int colBase = blockIdx.x * BN;
    int zb = blockIdx.z / zdiv, zh = blockIdx.z - zb * zdiv;
    const __half* Ab = A  + zb * sA1 + zh * sA2;
    const __half* Bb = Bm + zb * sB1 + zh * sB2;
    long long zco = zb * sC1 + zh * sC2;
    float*  Cf = (float*)C + zco;
    __half* Ch = (__half*)C + zco;
    const float* Rb = (EPI == 2) ? (Res + zco) : nullptr;

    const int KT = K / BK;

    auto load_tile = [&](int kt, int st){
        int k0 = kt * BK;
        uint32_t abase = sb + (uint32_t)(st * STGB);
        uint32_t bbase = abase + (uint32_t)ABYT;
        #pragma unroll
        for (int i = 0; i < BM*8/256; i++){
            int c = tid + i*256;
            int r = c >> 3, kc = c & 7;
            int gr = rowBase + r;
            const __half* src = Ab + (long long)min(gr, M-1) * lda + k0 + kc*8;
            cp16(abase + SWZ128(r*128 + kc*16), src, (gr < M) ? 16 : 0);
        }
        #pragma unroll
        for (int i = 0; i < BN*8/256; i++){
            int c = tid + i*256;
            int r = c >> 3, kc = c & 7;
            int gn = colBase + r;
            const __half* src = Bb + (long long)min(gn, Nn-1) * ldb + k0 + kc*8;
            cp16(bbase + SWZ128(r*128 + kc*16), src, (gn < Nn) ? 16 : 0);
        }
        CP_COMMIT();
    };

    float acc[2][NT][4];
    #pragma unroll
    for (int mt = 0; mt < 2; mt++)
        #pragma unroll
        for (int nt = 0; nt < NT; nt++)
            #pragma unroll
            for (int j = 0; j < 4; j++) acc[mt][nt][j] = 0.0f;

    int pf = (S-1 < KT) ? S-1 : KT;
    for (int t = 0; t < pf; t++) load_tile(t, t % S);

    int rfrag = lane >> 2, cfrag = lane & 3;
    // ldmatrix per-lane constants
    int lane15 = lane & 15;
    uint32_t lx = (uint32_t)(((lane >> 4) << 2) ^ (lane & 7));   // chunk-xor constant
    uint32_t aRowOff = (uint32_t)(wm*32 + lane15) * 128u;        // + mt*2048
    uint32_t bRowOff = (uint32_t)(wn*WN + lane15) * 128u;        // + p*2048

    uint32_t afr[2][2][4];        // [buf][mt][4]
    uint32_t bfr[2][NP2][4];      // [buf][p][4]

    auto load_frags = [&](uint32_t aAddr, uint32_t bAddr, int ks, int buf){
        uint32_t koff = (uint32_t)((ks ^ (int)lx) << 4);
        #pragma unroll
        for (int mt = 0; mt < 2; mt++)
            ldsm4(afr[buf][mt][0], afr[buf][mt][1], afr[buf][mt][2], afr[buf][mt][3],
                  aAddr + mt*2048u + koff);
        #pragma unroll
        for (int p = 0; p < NP2; p++)
            ldsm4(bfr[buf][p][0], bfr[buf][p][1], bfr[buf][p][2], bfr[buf][p][3],
                  bAddr + p*2048u + koff);
    };

    for (int kt = 0; kt < KT; kt++){
        if (kt == KT-1) cp_wait<0>(); else cp_wait<S-2>();
        __syncthreads();
        if (kt + S - 1 < KT) load_tile(kt + S - 1, (kt + S - 1) % S);

        uint32_t abase = sb + (uint32_t)((kt % S) * STGB);
        uint32_t bbase = abase + (uint32_t)ABYT;
        uint32_t aAddr = abase + aRowOff;
        uint32_t bAddr = bbase + bRowOff;
        load_frags(aAddr, bAddr, 0, 0);
        #pragma unroll
        for (int ks = 0; ks < 4; ks++){
            int cur = ks & 1;
            if (ks < 3) load_frags(aAddr, bAddr, ks+1, cur ^ 1);
            #pragma unroll
            for (int p = 0; p < NP2; p++){
                mma16(acc[0][2*p],   afr[cur][0], bfr[cur][p][0], bfr[cur][p][2]);
                mma16(acc[1][2*p],   afr[cur][1], bfr[cur][p][0], bfr[cur][p][2]);
                mma16(acc[0][2*p+1], afr[cur][0], bfr[cur][p][1], bfr[cur][p][3]);
                mma16(acc[1][2*p+1], afr[cur][1], bfr[cur][p][1], bfr[cur][p][3]);
            }
        }
    }

    if (EPI == 5){
        // ---- fused softmax epilogue: rows over cols [0, 197) ----
        __syncthreads();                       // smem reuse safety
        float* redm = smf;                     // [WCOLS][BM]
        float* reds = smf + WCOLS*BM;          // [WCOLS][BM]
        #pragma unroll
        for (int mt = 0; mt < 2; mt++)
            #pragma unroll
            for (int nt = 0; nt < NT; nt++)
                #pragma unroll
                for (int j = 0; j < 4; j++){
                    int gc = colBase + wn*WN + nt*8 + cfrag*2 + (j & 1);
                    acc[mt][nt][j] = (gc < N_) ? acc[mt][nt][j] * 0.125f : -1e30f;
                }
        float rmax[2][2];
        #pragma unroll
        for (int mt = 0; mt < 2; mt++)
            #pragma unroll
            for (int jr = 0; jr < 2; jr++){
                float m = -1e30f;
                #pragma unroll
                for (int nt = 0; nt < NT; nt++)
                    m = fmaxf(m, fmaxf(acc[mt][nt][jr*2], acc[mt][nt][jr*2+1]));
                m = fmaxf(m, __shfl_xor_sync(0xffffffffu, m, 1));
                m = fmaxf(m, __shfl_xor_sync(0xffffffffu, m, 2));
                rmax[mt][jr] = m;
            }
        if (cfrag == 0){
            #pragma unroll
            for (int mt = 0; mt < 2; mt++)
                #pragma unroll
                for (int jr = 0; jr < 2; jr++)
                    redm[wn*BM + wm*32 + mt*16 + jr*8 + rfrag] = rmax[mt][jr];
        }
        __syncthreads();
        float gmax[2][2], rsum[2][2];
        #pragma unroll
        for (int mt = 0; mt < 2; mt++)
            #pragma unroll
            for (int jr = 0; jr < 2; jr++){
                int rl = wm*32 + mt*16 + jr*8 + rfrag;
                float m = -1e30f;
                #pragma unroll
                for (int c = 0; c < WCOLS; c++)
                    m = fmaxf(m, redm[c*BM + rl]);
                gmax[mt][jr] = m;
                rsum[mt][jr] = 0.0f;
            }
        #pragma unroll
        for (int mt = 0; mt < 2; mt++)
            #pragma unroll
            for (int nt = 0; nt < NT; nt++)
                #pragma unroll
                for (int j = 0; j < 4; j++){
                    int gc = colBase + wn*WN + nt*8 + cfrag*2 + (j & 1);
                    float e = (gc < N_) ? __expf(acc[mt][nt][j] - gmax[mt][j>>1]) : 0.0f;
                    acc[mt][nt][j] = e;
                    rsum[mt][j>>1] += e;
                }
        #pragma unroll
        for (int mt = 0; mt < 2; mt++)
            #pragma unroll
            for (int jr = 0; jr < 2; jr++){
                float s = rsum[mt][jr];
                s += __shfl_xor_sync(0xffffffffu, s, 1);
                s += __shfl_xor_sync(0xffffffffu, s, 2);
                rsum[mt][jr] = s;
            }
        if (cfrag == 0){
            #pragma unroll
            for (int mt = 0; mt < 2; mt++)
                #pragma unroll
                for (int jr = 0; jr < 2; jr++)
                    reds[wn*BM + wm*32 + mt*16 + jr*8 + rfrag] = rsum[mt][jr];
        }
        __syncthreads();
        #pragma unroll
        for (int mt = 0; mt < 2; mt++)
            #pragma unroll
            for (int jr = 0; jr < 2; jr++){
                int rl = wm*32 + mt*16 + jr*8 + rfrag;
                int gr = rowBase + rl;
                if (gr >= M) continue;
                float ssum = 0.0f;
                #pragma unroll
                for (int c = 0; c < WCOLS; c++) ssum += reds[c*BM + rl];
                float inv = 1.0f / ssum;
                #pragma unroll
                for (int nt = 0; nt < NT; nt++){
                    int gc0 = colBase + wn*WN + nt*8 + cfrag*2;
                    if (gc0 >= NPAD) continue;
                    *(__half2*)(Ch + (long long)gr * ldc + gc0) =
                        __floats2half2_rn(acc[mt][nt][jr*2+0] * inv,
                                          acc[mt][nt][jr*2+1] * inv);
                }
            }
    } else {
        // ---- generic vectorized epilogue ----
        int seg = (EPI == 4) ? (colBase / 768) : 0;
        #pragma unroll
        for (int mt = 0; mt < 2; mt++){
            #pragma unroll
            for (int jr = 0; jr < 2; jr++){
                int gr = rowBase + wm*32 + mt*16 + jr*8 + rfrag;
                if (gr >= M) continue;
                #pragma unroll
                for (int nt = 0; nt < NT; nt++){
                    int gc = colBase + wn*WN + nt*8 + cfrag*2;
                    if (gc >= Nn) continue;
                    float v0 = acc[mt][nt][jr*2+0];
                    float v1 = acc[mt][nt][jr*2+1];
                    if (bias){
                        float2 b2 = *(const float2*)(bias + gc);
                        v0 += b2.x; v1 += b2.y;
                    }
                    if (EPI == 1){ v0 = gelu_f(v0); v1 = gelu_f(v1); }
                    if (EPI == 2){
                        float2 r2 = *(const float2*)(Rb + (long long)gr * ldc + gc);
                        v0 += r2.x; v1 += r2.y;
                    }
                    if (EPI == 4){
                        int gcl = gc - seg * 768;
                        if (seg < 2){
                            __half* dst = (__half*)((seg == 0) ? C : C2);
                            *(__half2*)(dst + (long long)gr * 768 + gcl) = __floats2half2_rn(v0, v1);
                        } else {
                            __half* vtb = (__half*)C3;
                            int b = gr / N_, n = gr % N_;
                            int hh = gcl >> 6, d = gcl & 63;
                            vtb[(((long long)b * HEADS_ + hh) * DH_ + d    ) * NPAD + n] = __float2half_rn(v0);
                            vtb[(((long long)b * HEADS_ + hh) * DH_ + d + 1) * NPAD + n] = __float2half_rn(v1);
                        }
                    } else if (RND){
                        *(__half2*)(Ch + (long long)gr * ldc + gc) = __floats2half2_rn(v0, v1);
                    } else {
                        *(float2*)(Cf + (long long)gr * ldc + gc) = make_float2(v0, v1);
                    }
                }
            }
        }
    }
}

// ---------------- weight transpose fp32 -> half (with row offset) ----------
__global__ void transpose_kernel(const float* __restrict__ in, __half* __restrict__ out,
                                 int R, int C, int ldo, int rowOff,
                                 long long inb, long long outb){
    __shared__ float t[32][33];
    const float* ip = in + blockIdx.z * inb;
    __half* op = out + blockIdx.z * outb;
    int c0 = blockIdx.x * 32, r0 = blockIdx.y * 32;
    int x = threadIdx.x, y = threadIdx.y;
    #pragma unroll
    for (int i = 0; i < 32; i += 8){
        int r = r0 + y + i, c = c0 + x;
        if (r < R && c < C) t[y+i][x] = ip[(long long)r*C + c];
    }
    __syncthreads();
    #pragma unroll
    for (int i = 0; i < 32; i += 8){
        int r = c0 + y + i, c = r0 + x;
        if (r < C && c < R) op[(long long)(rowOff + r)*ldo + c] = __float2half_rn(t[x][y+i]);
    }
}

// ---------------- misc small kernels ---------------------------------------
__global__ void zeroh_kernel(__half* __restrict__ p, long long n){
    long long stride = (long long)gridDim.x * blockDim.x;
    for (long long i = (long long)blockIdx.x * blockDim.x + threadIdx.x; i < n; i += stride)
        p[i] = __float2half_rn(0.0f);
}
__global__ void tohalf_kernel(const float* __restrict__ in, __half* __restrict__ out, long long n){
    long long stride = (long long)gridDim.x * blockDim.x;
    for (long long i = (long long)blockIdx.x * blockDim.x + threadIdx.x; i < n; i += stride)
        out[i] = __float2half_rn(in[i]);
}
__global__ void stackb_kernel(const float* __restrict__ bq, const float* __restrict__ bk,
                              const float* __restrict__ bv, float* __restrict__ out){
    int i = blockIdx.x * blockDim.x + threadIdx.x;
    if (i >= L_ * 3 * D_) return;
    int l = i / (3*D_), j = i % (3*D_);
    float v = (j < D_) ? bq[l*D_ + j] : (j < 2*D_) ? bk[l*D_ + j - D_] : bv[l*D_ + j - 2*D_];
    out[i] = v;
}

// ---------------- im2col for 16x16 stride-16 patches -> half ---------------
__global__ void im2col_kernel(const float* __restrict__ img, __half* __restrict__ out) {
    long long total = (long long)MPATCH * 768;
    long long stride = (long long)gridDim.x * blockDim.x;
    for (long long idx = (long long)blockIdx.x * blockDim.x + threadIdx.x; idx < total; idx += stride) {
        int kk = (int)(idx % 768);
        long long row = idx / 768;
        int b = (int)(row / NP_);
        int p = (int)(row % NP_);
        int ph = p / 14, pw = p % 14;
        int c = kk >> 8;
        int rem = kk & 255;
        int i = rem >> 4, j = rem & 15;
        out[idx] = __float2half_rn(img[(((long long)b*3 + c)*224 + (ph*16 + i))*224 + (pw*16 + j)]);
    }
}

// ---------------- cls + patches + pos_emb assemble (fp32 residual init) ----
__global__ void assemble_kernel(const float* __restrict__ po, const float* __restrict__ cls,
                                const float* __restrict__ pos, float* __restrict__ x) {
    long long total = (long long)MTOK * D_;
    long long stride = (long long)gridDim.x * blockDim.x;
    for (long long idx = (long long)blockIdx.x * blockDim.x + threadIdx.x; idx < total; idx += stride) {
        int d = (int)(idx % D_);
        long long row = idx / D_;
        int b = (int)(row / N_);
        int n = (int)(row % N_);
        float v = (n == 0) ? cls[d] : po[((long long)b*NP_ + (n-1))*D_ + d];
        x[idx] = v + pos[(long long)n*D_ + d];
    }
}

// ---------------- LayerNorm: warp per row of 768, fp32 in -> half out ------
__global__ void ln_kernel(const float* __restrict__ in, __half* __restrict__ out,
                          const float* __restrict__ g, const float* __restrict__ bb, int rows) {
    int w = (blockIdx.x * blockDim.x + threadIdx.x) >> 5;
    int lane = threadIdx.x & 31;
    if (w >= rows) return;
    const float4* ip = (const float4*)(in + (long long)w * D_);
    float4 vv[6];
    float s = 0.f, q = 0.f;
    #pragma unroll
    for (int j = 0; j < 6; j++){
        vv[j] = ip[lane + j*32];
        s += vv[j].x + vv[j].y + vv[j].z + vv[j].w;
        q += vv[j].x*vv[j].x + vv[j].y*vv[j].y + vv[j].z*vv[j].z + vv[j].w*vv[j].w;
    }
    #pragma unroll
    for (int o = 16; o; o >>= 1){
        s += __shfl_xor_sync(0xffffffffu, s, o);
        q += __shfl_xor_sync(0xffffffffu, q, o);
    }
    float mu = s * (1.0f/D_);
    float rs = rsqrtf(q * (1.0f/D_) - mu*mu + 1e-5f);
    __half2* op = (__half2*)(out + (long long)w * D_);
    const float4* gp = (const float4*)g;
    const float4* bp = (const float4*)bb;
    #pragma unroll
    for (int j = 0; j < 6; j++){
        int i = lane + j*32;
        float4 gg = gp[i], b2 = bp[i], v = vv[j];
        op[2*i]   = __floats2half2_rn((v.x-mu)*rs*gg.x + b2.x, (v.y-mu)*rs*gg.y + b2.y);
        op[2*i+1] = __floats2half2_rn((v.z-mu)*rs*gg.z + b2.z, (v.w-mu)*rs*gg.w + b2.w);
    }
}

// ---------------- mean pool over tokens ------------------------------------
__global__ void pool_kernel(const float* __restrict__ x, float* __restrict__ out) {
    int b = blockIdx.x;
    for (int d = threadIdx.x; d < D_; d += blockDim.x) {
        float s = 0.0f;
        const float* p = x + ((long long)b * N_) * D_ + d;
        for (int n = 0; n < N_; n++) s += p[(long long)n * D_];
        out[b*D_ + d] = s * (1.0f / N_);
    }
}

// ---------------- launcher --------------------------------------------------
extern "C" void kernel_launch(void* const* d_in, const int* in_sizes, int n_in,
                              void* d_out, int out_size) {
    const float* imgs    = (const float*)d_in[0];
    const float* patch_w = (const float*)d_in[1];
    const float* patch_b = (const float*)d_in[2];
    const float* cls_tok = (const float*)d_in[3];
    const float* pos_emb = (const float*)d_in[4];
    const float* ln1_g   = (const float*)d_in[5];
    const float* ln1_b   = (const float*)d_in[6];
    const float* wq      = (const float*)d_in[7];
    const float* bq      = (const float*)d_in[8];
    const float* wk      = (const float*)d_in[9];
    const float* bk      = (const float*)d_in[10];
    const float* wv      = (const float*)d_in[11];
    const float* bv      = (const float*)d_in[12];
    const float* wo      = (const float*)d_in[13];
    const float* bo      = (const float*)d_in[14];
    const float* ln2_g   = (const float*)d_in[15];
    const float* ln2_b   = (const float*)d_in[16];
    const float* w1      = (const float*)d_in[17];
    const float* b1      = (const float*)d_in[18];
    const float* w2      = (const float*)d_in[19];
    const float* b2      = (const float*)d_in[20];
    const float* hn_g    = (const float*)d_in[21];
    const float* hn_b    = (const float*)d_in[22];
    const float* hw      = (const float*)d_in[23];
    const float* hb      = (const float*)d_in[24];
    float* outp = (float*)d_out;

    float *x,*po,*pool; float *bqkv;
    __half *h,*q,*k,*o,*mlp,*sc,*vt,*col,*pln,*pwr;
    __half *wqkvt,*wot,*w1t,*w2t,*hwt;
    cudaGetSymbolAddress((void**)&x,    g_x);
    cudaGetSymbolAddress((void**)&h,    g_h);
    cudaGetSymbolAddress((void**)&q,    g_q);
    cudaGetSymbolAddress((void**)&k,    g_k);
    cudaGetSymbolAddress((void**)&o,    g_o);
    cudaGetSymbolAddress((void**)&mlp,  g_mlp);
    cudaGetSymbolAddress((void**)&sc,   g_sc);
    cudaGetSymbolAddress((void**)&vt,   g_vt);
    cudaGetSymbolAddress((void**)&col,  g_col);
    cudaGetSymbolAddress((void**)&po,   g_po);
    cudaGetSymbolAddress((void**)&pool, g_pool);
    cudaGetSymbolAddress((void**)&pln,  g_pln);
    cudaGetSymbolAddress((void**)&pwr,  g_pwr);
    cudaGetSymbolAddress((void**)&wqkvt,g_wqkvt);
    cudaGetSymbolAddress((void**)&bqkv, g_bqkv);
    cudaGetSymbolAddress((void**)&wot,  g_wot);
    cudaGetSymbolAddress((void**)&w1t,  g_w1t);
    cudaGetSymbolAddress((void**)&w2t,  g_w2t);
    cudaGetSymbolAddress((void**)&hwt,  g_hwt);

    const int SM128 = 3 * (128 + 128) * 128;   // 98304 B  (BM=128/BN=128, 2 CTA/SM)
    const int SMQK  = (64 + 256) * 128;        // 40960 B  (QK, KT=1, single stage)
    const int SM64N = 3 * (64 + 128) * 128;    // 73728 B  (BM=64/BN=128, 3 CTA/SM)
    const int SMPV  = 3 * (64 + 64) * 128;     // 49152 B  (BM=64/BN=64, 3 CTA/SM)
    cudaFuncSetAttribute((const void*)tgemm<128,128,0,false,2>, cudaFuncAttributeMaxDynamicSharedMemorySize, SM128);
    cudaFuncSetAttribute((const void*)tgemm<128,128,4,true,2>,  cudaFuncAttributeMaxDynamicSharedMemorySize, SM128);
    cudaFuncSetAttribute((const void*)tgemm<64,256,5,false,2>,  cudaFuncAttributeMaxDynamicSharedMemorySize, SMQK);
    cudaFuncSetAttribute((const void*)tgemm<64,64,0,true,3>,    cudaFuncAttributeMaxDynamicSharedMemorySize, SMPV);
    cudaFuncSetAttribute((const void*)tgemm<64,128,2,false,3>,  cudaFuncAttributeMaxDynamicSharedMemorySize, SM64N);
    cudaFuncSetAttribute((const void*)tgemm<128,128,1,true,2>,  cudaFuncAttributeMaxDynamicSharedMemorySize, SM128);

    dim3 tb(32,8);
    // Launches 2 and 3 are the SAME patch GEMM (idempotent) — the harness
    // prepends 2-3 launches, so ncu's "-s 5 -c 1" lands on one of these.
    im2col_kernel<<<4096, 256>>>(imgs, col);                                        // 0
    tohalf_kernel<<<1024, 256>>>(patch_w, pwr, (long long)D_*768);                  // 1
    tgemm<128,128,0,false,2><<<dim3(6,49,1), 256, SM128>>>(col, pwr, patch_b, nullptr,// 2
        po, nullptr, nullptr, MPATCH, D_, 768, 768, 768, 768, 1, 0,0, 0,0, 0,0);
    tgemm<128,128,0,false,2><<<dim3(6,49,1), 256, SM128>>>(col, pwr, patch_b, nullptr,// 3 (dup, for ncu)
        po, nullptr, nullptr, MPATCH, D_, 768, 768, 768, 768, 1, 0,0, 0,0, 0,0);
    assemble_kernel<<<4096, 256>>>(po, cls_tok, pos_emb, x);                        // 4
    zeroh_kernel<<<1024, 256>>>(vt, (long long)B_*HEADS_*DH_*NPAD);                 // pad tokens of V^T stay 0
    transpose_kernel<<<dim3(32,24,1), tb>>>(hw, hwt, D_, NC_, D_, 0, 0, 0);

    // weight transposes -> [N,K] K-major half
    transpose_kernel<<<dim3(24,24,L_), tb>>>(wq, wqkvt, D_, D_, D_, 0,     (long long)D_*D_, (long long)3*D_*D_);
    transpose_kernel<<<dim3(24,24,L_), tb>>>(wk, wqkvt, D_, D_, D_, D_,    (long long)D_*D_, (long long)3*D_*D_);
    transpose_kernel<<<dim3(24,24,L_), tb>>>(wv, wqkvt, D_, D_, D_, 2*D_,  (long long)D_*D_, (long long)3*D_*D_);
    transpose_kernel<<<dim3(24,24,L_), tb>>>(wo, wot,   D_, D_, D_, 0,     (long long)D_*D_, (long long)D_*D_);
    transpose_kernel<<<dim3(96,24,L_), tb>>>(w1, w1t,   D_, MLP_, D_, 0,   (long long)D_*MLP_, (long long)D_*MLP_);
    transpose_kernel<<<dim3(24,96,L_), tb>>>(w2, w2t,   MLP_, D_, MLP_, 0, (long long)D_*MLP_, (long long)D_*MLP_);
    stackb_kernel<<<(L_*3*D_ + 255)/256, 256>>>(bq, bk, bv, bqkv);

    const long long sQb = (long long)N_*D_, sQh = DH_;
    const long long sSb = (long long)HEADS_*N_*NPAD, sSh = (long long)N_*NPAD;
    const long long sVb = (long long)HEADS_*DH_*NPAD, sVh = (long long)DH_*NPAD;

    for (int i = 0; i < L_; i++) {
        const __half* Wqkv = wqkvt + (long long)i*3*D_*D_;
        const float*  Bqkv = bqkv  + (long long)i*3*D_;
        const __half* Wo = wot + (long long)i*D_*D_;   const float* Bo = bo + (long long)i*D_;
        const __half* W1 = w1t + (long long)i*D_*MLP_; const float* B1 = b1 + (long long)i*MLP_;
        const __half* W2 = w2t + (long long)i*D_*MLP_; const float* B2 = b2 + (long long)i*D_;

        ln_kernel<<<(MTOK*32+255)/256, 256>>>(x, h, ln1_g + (long long)i*D_, ln1_b + (long long)i*D_, MTOK);

        // fused QKV: [6304 x 2304] = h @ Wqkv^T ; routes to q, k, vt
        tgemm<128,128,4,true,2><<<dim3(18,50,1), 256, SM128>>>(h, Wqkv, Bqkv, nullptr,
            q, k, vt, MTOK, 3*D_, D_, D_, D_, D_, 1, 0,0, 0,0, 0,0);

        // S = softmax(Q K^T / 8) per (b,h): BM=64 tile (no spill), KT=1, 1-stage smem
        tgemm<64,256,5,false,2><<<dim3(1,4,B_*HEADS_), 256, SMQK>>>(q, k, nullptr, nullptr,
            sc, nullptr, nullptr, N_, N_, DH_, D_, D_, NPAD, HEADS_,
            sQb, sQh, sQb, sQh, sSb, sSh);

        // O = P @ V per (b,h): [197 x 64], K=256 (zero-padded), 3 CTA/SM
        tgemm<64,64,0,true,3><<<dim3(1,4,B_*HEADS_), 256, SMPV>>>(sc, vt, nullptr, nullptr,
            o, nullptr, nullptr, N_, DH_, NPAD, NPAD, NPAD, D_, HEADS_,
            sSb, sSh, sVb, sVh, sQb, sQh);

        // x = x + O @ Wo^T + bo  (fp32 residual out), BM=64 @ 3 CTA/SM
        tgemm<64,128,2,false,3><<<dim3(6,99,1), 256, SM64N>>>(o, Wo, Bo, x,
            x, nullptr, nullptr, MTOK, D_, D_, D_, D_, D_, 1, 0,0, 0,0, 0,0);

        ln_kernel<<<(MTOK*32+255)/256, 256>>>(x, h, ln2_g + (long long)i*D_, ln2_b + (long long)i*D_, MTOK);

        tgemm<128,128,1,true,2><<<dim3(24,50,1), 256, SM128>>>(h, W1, B1, nullptr,
            mlp, nullptr, nullptr, MTOK, MLP_, D_, D_, D_, MLP_, 1, 0,0, 0,0, 0,0);
        tgemm<64,128,2,false,3><<<dim3(6,99,1), 256, SM64N>>>(mlp, W2, B2, x,
            x, nullptr, nullptr, MTOK, D_, MLP_, MLP_, MLP_, D_, 1, 0,0, 0,0, 0,0);
    }

    pool_kernel<<<B_, 256>>>(x, pool);
    ln_kernel<<<(B_*32+255)/256, 256>>>(pool, pln, hn_g, hn_b, B_);
    tgemm<128,128,0,false,2><<<dim3(8,1,1), 256, SM128>>>(pln, hwt, hb, nullptr,
        outp, nullptr, nullptr, B_, NC_, D_, D_, D_, NC_, 1, 0,0, 0,0, 0,0);
}

// round 15
// speedup vs baseline: 1.0140x; 1.0140x over previous
#include <cuda_runtime.h>
#include <cuda_fp16.h>
#include <cstdint>
#include <math.h>

#define B_ 32
#define D_ 768
#define L_ 12
#define HEADS_ 12
#define DH_ 64
#define MLP_ 3072
#define NC_ 1000
#define N_ 197
#define NP_ 196
#define NPAD 256
#define MTOK (B_*N_)       // 6304
#define MPATCH (B_*NP_)    // 6272

// ---------------- scratch (device globals; no runtime allocation) ----------
__device__ float  g_x  [MTOK*D_];                         // residual stream fp32
__device__ __half g_h  [MTOK*D_];
__device__ __half g_qkv[(long long)MTOK*3*D_];            // fused q|k|v, ld=2304
__device__ __half g_o  [MTOK*D_];
__device__ __half g_mlp[(long long)MTOK*MLP_];
__device__ __half g_sc [(long long)B_*HEADS_*N_*NPAD];    // probs, ld=256
__device__ __half g_vt [(long long)B_*HEADS_*DH_*NPAD];   // V^T per head, ld=256
__device__ __half g_col[(long long)MPATCH*768];
__device__ float  g_po [(long long)MPATCH*D_];
__device__ float  g_pool[B_*D_];
__device__ __half g_pln [B_*D_];
__device__ __half g_pwr[(long long)D_*768];               // patch_w as half
// transposed (half) weights, [N,K] K-major
__device__ __half g_wqkvt[(long long)L_*3*D_*D_];         // stacked q|k|v, 2304 x 768
__device__ float  g_bqkv [(long long)L_*3*D_];            // stacked biases (fp32)
__device__ __half g_wot[(long long)L_*D_*D_];
__device__ __half g_w1t[(long long)L_*D_*MLP_];
__device__ __half g_w2t[(long long)L_*D_*MLP_];
__device__ __half g_hwt[(long long)NC_*D_];

__device__ __forceinline__ float gelu_f(float x) {
    float x3 = x*x*x;
    return 0.5f*x*(1.0f + tanhf(0.7978845608028654f*(x + 0.044715f*x3)));
}

// ---------------- PTX helpers ----------------------------------------------
__device__ __forceinline__ uint32_t smem_u32(const void* p){
    uint32_t a;
    asm("{ .reg .u64 t; cvta.to.shared.u64 t, %1; cvt.u32.u64 %0, t; }" : "=r"(a) : "l"(p));
    return a;
}
__device__ __forceinline__ void cp16(uint32_t dst, const void* src, int srcbytes){
    asm volatile("cp.async.cg.shared.global [%0], [%1], 16, %2;"
                 :: "r"(dst), "l"(src), "r"(srcbytes));
}
#define CP_COMMIT() asm volatile("cp.async.commit_group;" ::: "memory")
template<int Nw> __device__ __forceinline__ void cp_wait(){
    asm volatile("cp.async.wait_group %0;" :: "n"(Nw) : "memory");
}
// fp16 mma: D += A*B, m16n8k16, fp32 accumulate
__device__ __forceinline__ void mma16(float* d, const uint32_t* a, uint32_t b0, uint32_t b1){
    asm volatile("mma.sync.aligned.m16n8k16.row.col.f32.f16.f16.f32 "
        "{%0,%1,%2,%3}, {%4,%5,%6,%7}, {%8,%9}, {%0,%1,%2,%3};"
        : "+f"(d[0]), "+f"(d[1]), "+f"(d[2]), "+f"(d[3])
        : "r"(a[0]), "r"(a[1]), "r"(a[2]), "r"(a[3]), "r"(b0), "r"(b1));
}
__device__ __forceinline__ void ldsm4(uint32_t& r0, uint32_t& r1, uint32_t& r2, uint32_t& r3,
                                      uint32_t addr){
    asm volatile("ldmatrix.sync.aligned.m8n8.x4.shared.b16 {%0,%1,%2,%3}, [%4];"
        : "=r"(r0), "=r"(r1), "=r"(r2), "=r"(r3) : "r"(addr));
}
#define SWZ128(o) ((o) ^ (((o) >> 3) & 0x70))

// ---------------- mma.sync fp16 batched GEMM --------------------------------
// C[M,N] = A[M,K] @ B[N,K]^T  (both half, K-major). K must be a multiple of 64.
// BK = 64 halves = one 128B SW128 atom per row. Fragments loaded via
// ldmatrix.x4 with per-lane swizzle constant lx; A and B consume the identical
// chunk permutation (ks, ks+4) -> exact. Register ping-pong on fragments.
// BM in {64,128}: warp grid is (BM/32) x (8/(BM/32)).
// EPI: 0 bias, 1 bias+gelu, 2 bias+residual(float out),
//      5 fused softmax (scores -> probs half, scale 0.125, valid cols < 197)
// RND=true: output is __half; RND=false: output is float (EPI 5 always half).
template<int BM, int BN, int EPI, bool RND>
__global__ void __launch_bounds__(256, 2)
tgemm(const __half* __restrict__ A, const __half* __restrict__ Bm,
      const float* __restrict__ bias, const float* __restrict__ Res,
      void* __restrict__ C,
      int M, int Nn, int K, int lda, int ldb, int ldc, int zdiv,
      long long sA1, long long sA2, long long sB1, long long sB2,
      long long sC1, long long sC2)
{
    constexpr int BK = 64, S = 3;
    constexpr int ABYT = BM * 128;                 // bytes per A stage
    constexpr int BBYT = BN * 128;
    constexpr int STGB = ABYT + BBYT;
    constexpr int WROWS = BM / 32;                 // warps along M
    constexpr int WCOLS = 8 / WROWS;               // warps along N
    constexpr int WN  = BN / WCOLS;                // warp tile N
    constexpr int NT  = WN / 8;
    constexpr int NP2 = NT / 2;

    extern __shared__ float smf[];
    uint32_t sb = smem_u32(smf);
    int tid = threadIdx.x, lane = tid & 31, wid = tid >> 5;
    int wm = wid % WROWS, wn = wid / WROWS;

    int rowBase = blockIdx.y * BM;
    int colBase = blockIdx.x * BN;
    int zb = blockIdx.z / zdiv, zh = blockIdx.z - zb * zdiv;
    const __half* Ab = A  + zb * sA1 + zh * sA2;
    const __half* Bb = Bm + zb * sB1 + zh * sB2;
    long long zco = zb * sC1 + zh * sC2;
    float*  Cf = (float*)C + zco;
    __half* Ch = (__half*)C + zco;
    const float* Rb = (EPI == 2) ? (Res + zco) : nullptr;

    const int KT = K / BK;

    auto load_tile = [&](int kt, int st){
        int k0 = kt * BK;
        uint32_t abase = sb + (uint32_t)(st * STGB);
        uint32_t bbase = abase + (uint32_t)ABYT;
        #pragma unroll
        for (int i = 0; i < BM*8/256; i++){
            int c = tid + i*256;
            int r = c >> 3, kc = c & 7;
            int gr = rowBase + r;
            const __half* src = Ab + (long long)min(gr, M-1) * lda + k0 + kc*8;
            cp16(abase + SWZ128(r*128 + kc*16), src, (gr < M) ? 16 : 0);
        }
        #pragma unroll
        for (int i = 0; i < BN*8/256; i++){
            int c = tid + i*256;
            int r = c >> 3, kc = c & 7;
            int gn = colBase + r;
            const __half* src = Bb + (long long)min(gn, Nn-1) * ldb + k0 + kc*8;
            cp16(bbase + SWZ128(r*128 + kc*16), src, (gn < Nn) ? 16 : 0);
        }
        CP_COMMIT();
    };

    float acc[2][NT][4];
    #pragma unroll
    for (int mt = 0; mt < 2; mt++)
        #pragma unroll
        for (int nt = 0; nt < NT; nt++)
            #pragma unroll
            for (int j = 0; j < 4; j++) acc[mt][nt][j] = 0.0f;

    int pf = (S-1 < KT) ? S-1 : KT;
    for (int t = 0; t < pf; t++) load_tile(t, t % S);

    int rfrag = lane >> 2, cfrag = lane & 3;
    // ldmatrix per-lane constants
    int lane15 = lane & 15;
    uint32_t lx = (uint32_t)(((lane >> 4) << 2) ^ (lane & 7));   // chunk-xor constant
    uint32_t aRowOff = (uint32_t)(wm*32 + lane15) * 128u;        // + mt*2048
    uint32_t bRowOff = (uint32_t)(wn*WN + lane15) * 128u;        // + p*2048

    uint32_t afr[2][2][4];        // [buf][mt][4]
    uint32_t bfr[2][NP2][4];      // [buf][p][4]

    auto load_frags = [&](uint32_t aAddr, uint32_t bAddr, int ks, int buf){
        uint32_t koff = (uint32_t)((ks ^ (int)lx) << 4);
        #pragma unroll
        for (int mt = 0; mt < 2; mt++)
            ldsm4(afr[buf][mt][0], afr[buf][mt][1], afr[buf][mt][2], afr[buf][mt][3],
                  aAddr + mt*2048u + koff);
        #pragma unroll
        for (int p = 0; p < NP2; p++)
            ldsm4(bfr[buf][p][0], bfr[buf][p][1], bfr[buf][p][2], bfr[buf][p][3],
                  bAddr + p*2048u + koff);
    };

    for (int kt = 0; kt < KT; kt++){
        if (kt == KT-1) cp_wait<0>(); else cp_wait<S-2>();
        __syncthreads();
        if (kt + S - 1 < KT) load_tile(kt + S - 1, (kt + S - 1) % S);

        uint32_t abase = sb + (uint32_t)((kt % S) * STGB);
        uint32_t bbase = abase + (uint32_t)ABYT;
        uint32_t aAddr = abase + aRowOff;
        uint32_t bAddr = bbase + bRowOff;
        load_frags(aAddr, bAddr, 0, 0);
        #pragma unroll
        for (int ks = 0; ks < 4; ks++){
            int cur = ks & 1;
            if (ks < 3) load_frags(aAddr, bAddr, ks+1, cur ^ 1);
            #pragma unroll
            for (int p = 0; p < NP2; p++){
                mma16(acc[0][2*p],   afr[cur][0], bfr[cur][p][0], bfr[cur][p][2]);
                mma16(acc[1][2*p],   afr[cur][1], bfr[cur][p][0], bfr[cur][p][2]);
                mma16(acc[0][2*p+1], afr[cur][0], bfr[cur][p][1], bfr[cur][p][3]);
                mma16(acc[1][2*p+1], afr[cur][1], bfr[cur][p][1], bfr[cur][p][3]);
            }
        }
    }

    if (EPI == 5){
        // ---- fused softmax epilogue: rows over cols [0, 197) ----
        __syncthreads();                       // smem reuse safety
        float* redm = smf;                     // [WCOLS][BM]
        float* reds = smf + WCOLS*BM;          // [WCOLS][BM]
        #pragma unroll
        for (int mt = 0; mt < 2; mt++)
            #pragma unroll
            for (int nt = 0; nt < NT; nt++)
                #pragma unroll
                for (int j = 0; j < 4; j++){
                    int gc = colBase + wn*WN + nt*8 + cfrag*2 + (j & 1);
                    acc[mt][nt][j] = (gc < N_) ? acc[mt][nt][j] * 0.125f : -1e30f;
                }
        float rmax[2][2];
        #pragma unroll
        for (int mt = 0; mt < 2; mt++)
            #pragma unroll
            for (int jr = 0; jr < 2; jr++){
                float m = -1e30f;
                #pragma unroll
                for (int nt = 0; nt < NT; nt++)
                    m = fmaxf(m, fmaxf(acc[mt][nt][jr*2], acc[mt][nt][jr*2+1]));
                m = fmaxf(m, __shfl_xor_sync(0xffffffffu, m, 1));
                m = fmaxf(m, __shfl_xor_sync(0xffffffffu, m, 2));
                rmax[mt][jr] = m;
            }
        if (cfrag == 0){
            #pragma unroll
            for (int mt = 0; mt < 2; mt++)
                #pragma unroll
                for (int jr = 0; jr < 2; jr++)
                    redm[wn*BM + wm*32 + mt*16 + jr*8 + rfrag] = rmax[mt][jr];
        }
        __syncthreads();
        float gmax[2][2], rsum[2][2];
        #pragma unroll
        for (int mt = 0; mt < 2; mt++)
            #pragma unroll
            for (int jr = 0; jr < 2; jr++){
                int rl = wm*32 + mt*16 + jr*8 + rfrag;
                float m = -1e30f;
                #pragma unroll
                for (int c = 0; c < WCOLS; c++)
                    m = fmaxf(m, redm[c*BM + rl]);
                gmax[mt][jr] = m;
                rsum[mt][jr] = 0.0f;
            }
        #pragma unroll
        for (int mt = 0; mt < 2; mt++)
            #pragma unroll
            for (int nt = 0; nt < NT; nt++)
                #pragma unroll
                for (int j = 0; j < 4; j++){
                    int gc = colBase + wn*WN + nt*8 + cfrag*2 + (j & 1);
                    float e = (gc < N_) ? __expf(acc[mt][nt][j] - gmax[mt][j>>1]) : 0.0f;
                    acc[mt][nt][j] = e;
                    rsum[mt][j>>1] += e;
                }
        #pragma unroll
        for (int mt = 0; mt < 2; mt++)
            #pragma unroll
            for (int jr = 0; jr < 2; jr++){
                float s = rsum[mt][jr];
                s += __shfl_xor_sync(0xffffffffu, s, 1);
                s += __shfl_xor_sync(0xffffffffu, s, 2);
                rsum[mt][jr] = s;
            }
        if (cfrag == 0){
            #pragma unroll
            for (int mt = 0; mt < 2; mt++)
                #pragma unroll
                for (int jr = 0; jr < 2; jr++)
                    reds[wn*BM + wm*32 + mt*16 + jr*8 + rfrag] = rsum[mt][jr];
        }
        __syncthreads();
        #pragma unroll
        for (int mt = 0; mt < 2; mt++)
            #pragma unroll
            for (int jr = 0; jr < 2; jr++){
                int rl = wm*32 + mt*16 + jr*8 + rfrag;
                int gr = rowBase + rl;
                if (gr >= M) continue;
                float ssum = 0.0f;
                #pragma unroll
                for (int c = 0; c < WCOLS; c++) ssum += reds[c*BM + rl];
                float inv = 1.0f / ssum;
                #pragma unroll
                for (int nt = 0; nt < NT; nt++){
                    int gc0 = colBase + wn*WN + nt*8 + cfrag*2;
                    if (gc0 >= NPAD) continue;
                    *(__half2*)(Ch + (long long)gr * ldc + gc0) =
                        __floats2half2_rn(acc[mt][nt][jr*2+0] * inv,
                                          acc[mt][nt][jr*2+1] * inv);
                }
            }
    } else {
        // ---- generic vectorized epilogue ----
        #pragma unroll
        for (int mt = 0; mt < 2; mt++){
            #pragma unroll
            for (int jr = 0; jr < 2; jr++){
                int gr = rowBase + wm*32 + mt*16 + jr*8 + rfrag;
                if (gr >= M) continue;
                #pragma unroll
                for (int nt = 0; nt < NT; nt++){
                    int gc = colBase + wn*WN + nt*8 + cfrag*2;
                    if (gc >= Nn) continue;
                    float v0 = acc[mt][nt][jr*2+0];
                    float v1 = acc[mt][nt][jr*2+1];
                    if (bias){
                        float2 b2 = *(const float2*)(bias + gc);
                        v0 += b2.x; v1 += b2.y;
                    }
                    if (EPI == 1){ v0 = gelu_f(v0); v1 = gelu_f(v1); }
                    if (EPI == 2){
                        float2 r2 = *(const float2*)(Rb + (long long)gr * ldc + gc);
                        v0 += r2.x; v1 += r2.y;
                    }
                    if (RND){
                        *(__half2*)(Ch + (long long)gr * ldc + gc) = __floats2half2_rn(v0, v1);
                    } else {
                        *(float2*)(Cf + (long long)gr * ldc + gc) = make_float2(v0, v1);
                    }
                }
            }
        }
    }
}

// ---------------- per-head V transpose: vt[bh][d][n] = qkv[b,n][1536+h*64+d] -
__global__ void vtrans_kernel(const __half* __restrict__ qkv, __half* __restrict__ vt){
    __shared__ __half t[32][33];
    int bh = blockIdx.z;
    int b = bh / HEADS_, h = bh % HEADS_;
    const __half* ip = qkv + ((long long)b * N_) * 2304 + 1536 + h * DH_;
    __half* op = vt + ((long long)bh * DH_) * NPAD;
    int d0 = blockIdx.x * 32, n0 = blockIdx.y * 32;
    int x = threadIdx.x, y = threadIdx.y;
    #pragma unroll
    for (int i = 0; i < 32; i += 8){
        int n = n0 + y + i, d = d0 + x;
        if (n < N_ && d < DH_) t[y+i][x] = ip[(long long)n * 2304 + d];
    }
    __syncthreads();
    #pragma unroll
    for (int i = 0; i < 32; i += 8){
        int d = d0 + y + i, n = n0 + x;
        if (d < DH_ && n < N_) op[(long long)d * NPAD + n] = t[x][y+i];
    }
}

// ---------------- weight transpose fp32 -> half (with row offset) ----------
__global__ void transpose_kernel(const float* __restrict__ in, __half* __restrict__ out,
                                 int R, int C, int ldo, int rowOff,
                                 long long inb, long long outb){
    __shared__ float t[32][33];
    const float* ip = in + blockIdx.z * inb;
    __half* op = out + blockIdx.z * outb;
    int c0 = blockIdx.x * 32, r0 = blockIdx.y * 32;
    int x = threadIdx.x, y = threadIdx.y;
    #pragma unroll
    for (int i = 0; i < 32; i += 8){
        int r = r0 + y + i, c = c0 + x;
        if (r < R && c < C) t[y+i][x] = ip[(long long)r*C + c];
    }
    __syncthreads();
    #pragma unroll
    for (int i = 0; i < 32; i += 8){
        int r = c0 + y + i, c = r0 + x;
        if (r < C && c < R) op[(long long)(rowOff + r)*ldo + c] = __float2half_rn(t[x][y+i]);
    }
}

// ---------------- misc small kernels ---------------------------------------
__global__ void zeroh_kernel(__half* __restrict__ p, long long n){
    long long stride = (long long)gridDim.x * blockDim.x;
    for (long long i = (long long)blockIdx.x * blockDim.x + threadIdx.x; i < n; i += stride)
        p[i] = __float2half_rn(0.0f);
}
__global__ void tohalf_kernel(const float* __restrict__ in, __half* __restrict__ out, long long n){
    long long stride = (long long)gridDim.x * blockDim.x;
    for (long long i = (long long)blockIdx.x * blockDim.x + threadIdx.x; i < n; i += stride)
        out[i] = __float2half_rn(in[i]);
}
__global__ void stackb_kernel(const float* __restrict__ bq, const float* __restrict__ bk,
                              const float* __restrict__ bv, float* __restrict__ out){
    int i = blockIdx.x * blockDim.x + threadIdx.x;
    if (i >= L_ * 3 * D_) return;
    int l = i / (3*D_), j = i % (3*D_);
    float v = (j < D_) ? bq[l*D_ + j] : (j < 2*D_) ? bk[l*D_ + j - D_] : bv[l*D_ + j - 2*D_];
    out[i] = v;
}

// ---------------- im2col for 16x16 stride-16 patches -> half ---------------
__global__ void im2col_kernel(const float* __restrict__ img, __half* __restrict__ out) {
    long long total = (long long)MPATCH * 768;
    long long stride = (long long)gridDim.x * blockDim.x;
    for (long long idx = (long long)blockIdx.x * blockDim.x + threadIdx.x; idx < total; idx += stride) {
        int kk = (int)(idx % 768);
        long long row = idx / 768;
        int b = (int)(row / NP_);
        int p = (int)(row % NP_);
        int ph = p / 14, pw = p % 14;
        int c = kk >> 8;
        int rem = kk & 255;
        int i = rem >> 4, j = rem & 15;
        out[idx] = __float2half_rn(img[(((long long)b*3 + c)*224 + (ph*16 + i))*224 + (pw*16 + j)]);
    }
}

// ---------------- cls + patches + pos_emb assemble (fp32 residual init) ----
__global__ void assemble_kernel(const float* __restrict__ po, const float* __restrict__ cls,
                                const float* __restrict__ pos, float* __restrict__ x) {
    long long total = (long long)MTOK * D_;
    long long stride = (long long)gridDim.x * blockDim.x;
    for (long long idx = (long long)blockIdx.x * blockDim.x + threadIdx.x; idx < total; idx += stride) {
        int d = (int)(idx % D_);
        long long row = idx / D_;
        int b = (int)(row / N_);
        int n = (int)(row % N_);
        float v = (n == 0) ? cls[d] : po[((long long)b*NP_ + (n-1))*D_ + d];
        x[idx] = v + pos[(long long)n*D_ + d];
    }
}

// ---------------- LayerNorm: warp per row of 768, fp32 in -> half out ------
__global__ void ln_kernel(const float* __restrict__ in, __half* __restrict__ out,
                          const float* __restrict__ g, const float* __restrict__ bb, int rows) {
    int w = (blockIdx.x * blockDim.x + threadIdx.x) >> 5;
    int lane = threadIdx.x & 31;
    if (w >= rows) return;
    const float4* ip = (const float4*)(in + (long long)w * D_);
    float4 vv[6];
    float s = 0.f, q = 0.f;
    #pragma unroll
    for (int j = 0; j < 6; j++){
        vv[j] = ip[lane + j*32];
        s += vv[j].x + vv[j].y + vv[j].z + vv[j].w;
        q += vv[j].x*vv[j].x + vv[j].y*vv[j].y + vv[j].z*vv[j].z + vv[j].w*vv[j].w;
    }
    #pragma unroll
    for (int o = 16; o; o >>= 1){
        s += __shfl_xor_sync(0xffffffffu, s, o);
        q += __shfl_xor_sync(0xffffffffu, q, o);
    }
    float mu = s * (1.0f/D_);
    float rs = rsqrtf(q * (1.0f/D_) - mu*mu + 1e-5f);
    __half2* op = (__half2*)(out + (long long)w * D_);
    const float4* gp = (const float4*)g;
    const float4* bp = (const float4*)bb;
    #pragma unroll
    for (int j = 0; j < 6; j++){
        int i = lane + j*32;
        float4 gg = gp[i], b2 = bp[i], v = vv[j];
        op[2*i]   = __floats2half2_rn((v.x-mu)*rs*gg.x + b2.x, (v.y-mu)*rs*gg.y + b2.y);
        op[2*i+1] = __floats2half2_rn((v.z-mu)*rs*gg.z + b2.z, (v.w-mu)*rs*gg.w + b2.w);
    }
}

// ---------------- mean pool over tokens ------------------------------------
__global__ void pool_kernel(const float* __restrict__ x, float* __restrict__ out) {
    int b = blockIdx.x;
    for (int d = threadIdx.x; d < D_; d += blockDim.x) {
        float s = 0.0f;
        const float* p = x + ((long long)b * N_) * D_ + d;
        for (int n = 0; n < N_; n++) s += p[(long long)n * D_];
        out[b*D_ + d] = s * (1.0f / N_);
    }
}

// ---------------- launcher --------------------------------------------------
extern "C" void kernel_launch(void* const* d_in, const int* in_sizes, int n_in,
                              void* d_out, int out_size) {
    const float* imgs    = (const float*)d_in[0];
    const float* patch_w = (const float*)d_in[1];
    const float* patch_b = (const float*)d_in[2];
    const float* cls_tok = (const float*)d_in[3];
    const float* pos_emb = (const float*)d_in[4];
    const float* ln1_g   = (const float*)d_in[5];
    const float* ln1_b   = (const float*)d_in[6];
    const float* wq      = (const float*)d_in[7];
    const float* bq      = (const float*)d_in[8];
    const float* wk      = (const float*)d_in[9];
    const float* bk      = (const float*)d_in[10];
    const float* wv      = (const float*)d_in[11];
    const float* bv      = (const float*)d_in[12];
    const float* wo      = (const float*)d_in[13];
    const float* bo      = (const float*)d_in[14];
    const float* ln2_g   = (const float*)d_in[15];
    const float* ln2_b   = (const float*)d_in[16];
    const float* w1      = (const float*)d_in[17];
    const float* b1      = (const float*)d_in[18];
    const float* w2      = (const float*)d_in[19];
    const float* b2      = (const float*)d_in[20];
    const float* hn_g    = (const float*)d_in[21];
    const float* hn_b    = (const float*)d_in[22];
    const float* hw      = (const float*)d_in[23];
    const float* hb      = (const float*)d_in[24];
    float* outp = (float*)d_out;

    float *x,*po,*pool; float *bqkv;
    __half *h,*qkv,*o,*mlp,*sc,*vt,*col,*pln,*pwr;
    __half *wqkvt,*wot,*w1t,*w2t,*hwt;
    cudaGetSymbolAddress((void**)&x,    g_x);
    cudaGetSymbolAddress((void**)&h,    g_h);
    cudaGetSymbolAddress((void**)&qkv,  g_qkv);
    cudaGetSymbolAddress((void**)&o,    g_o);
    cudaGetSymbolAddress((void**)&mlp,  g_mlp);
    cudaGetSymbolAddress((void**)&sc,   g_sc);
    cudaGetSymbolAddress((void**)&vt,   g_vt);
    cudaGetSymbolAddress((void**)&col,  g_col);
    cudaGetSymbolAddress((void**)&po,   g_po);
    cudaGetSymbolAddress((void**)&pool, g_pool);
    cudaGetSymbolAddress((void**)&pln,  g_pln);
    cudaGetSymbolAddress((void**)&pwr,  g_pwr);
    cudaGetSymbolAddress((void**)&wqkvt,g_wqkvt);
    cudaGetSymbolAddress((void**)&bqkv, g_bqkv);
    cudaGetSymbolAddress((void**)&wot,  g_wot);
    cudaGetSymbolAddress((void**)&w1t,  g_w1t);
    cudaGetSymbolAddress((void**)&w2t,  g_w2t);
    cudaGetSymbolAddress((void**)&hwt,  g_hwt);

    const int SM128 = 3 * (128 + 128) * 128;   // 98304 B  (BM=128/BN=128, 2 CTA/SM)
    const int SMQK  = (64 + 256) * 128;        // 40960 B  (QK, KT=1, single stage)
    const int SM64  = 3 * (128 +  64) * 128;   // 73728 B  (PV, BM=128/BN=64)
    cudaFuncSetAttribute((const void*)tgemm<128,128,0,false>, cudaFuncAttributeMaxDynamicSharedMemorySize, SM128);
    cudaFuncSetAttribute((const void*)tgemm<128,128,0,true>,  cudaFuncAttributeMaxDynamicSharedMemorySize, SM128);
    cudaFuncSetAttribute((const void*)tgemm<64,256,5,false>,  cudaFuncAttributeMaxDynamicSharedMemorySize, SMQK);
    cudaFuncSetAttribute((const void*)tgemm<128,64,0,true>,   cudaFuncAttributeMaxDynamicSharedMemorySize, SM64);
    cudaFuncSetAttribute((const void*)tgemm<128,128,2,false>, cudaFuncAttributeMaxDynamicSharedMemorySize, SM128);
    cudaFuncSetAttribute((const void*)tgemm<128,128,1,true>,  cudaFuncAttributeMaxDynamicSharedMemorySize, SM128);

    dim3 tb(32,8);
    im2col_kernel<<<4096, 256>>>(imgs, col);
    tohalf_kernel<<<1024, 256>>>(patch_w, pwr, (long long)D_*768);
    tgemm<128,128,0,false><<<dim3(6,49,1), 256, SM128>>>(col, pwr, patch_b, nullptr,
        po, MPATCH, D_, 768, 768, 768, 768, 1, 0,0, 0,0, 0,0);
    assemble_kernel<<<4096, 256>>>(po, cls_tok, pos_emb, x);
    zeroh_kernel<<<1024, 256>>>(vt, (long long)B_*HEADS_*DH_*NPAD);   // pad tokens stay 0
    transpose_kernel<<<dim3(32,24,1), tb>>>(hw, hwt, D_, NC_, D_, 0, 0, 0);

    // weight transposes -> [N,K] K-major half
    transpose_kernel<<<dim3(24,24,L_), tb>>>(wq, wqkvt, D_, D_, D_, 0,     (long long)D_*D_, (long long)3*D_*D_);
    transpose_kernel<<<dim3(24,24,L_), tb>>>(wk, wqkvt, D_, D_, D_, D_,    (long long)D_*D_, (long long)3*D_*D_);
    transpose_kernel<<<dim3(24,24,L_), tb>>>(wv, wqkvt, D_, D_, D_, 2*D_,  (long long)D_*D_, (long long)3*D_*D_);
    transpose_kernel<<<dim3(24,24,L_), tb>>>(wo, wot,   D_, D_, D_, 0,     (long long)D_*D_, (long long)D_*D_);
    transpose_kernel<<<dim3(96,24,L_), tb>>>(w1, w1t,   D_, MLP_, D_, 0,   (long long)D_*MLP_, (long long)D_*MLP_);
    transpose_kernel<<<dim3(24,96,L_), tb>>>(w2, w2t,   MLP_, D_, MLP_, 0, (long long)D_*MLP_, (long long)D_*MLP_);
    stackb_kernel<<<(L_*3*D_ + 255)/256, 256>>>(bq, bk, bv, bqkv);

    const long long sQb = (long long)N_*2304, sQh = DH_;
    const long long sSb = (long long)HEADS_*N_*NPAD, sSh = (long long)N_*NPAD;
    const long long sVb = (long long)HEADS_*DH_*NPAD, sVh = (long long)DH_*NPAD;
    const long long sOb = (long long)N_*D_, sOh = DH_;

    for (int i = 0; i < L_; i++) {
        const __half* Wqkv = wqkvt + (long long)i*3*D_*D_;
        const float*  Bqkv = bqkv  + (long long)i*3*D_;
        const __half* Wo = wot + (long long)i*D_*D_;   const float* Bo = bo + (long long)i*D_;
        const __half* W1 = w1t + (long long)i*D_*MLP_; const float* B1 = b1 + (long long)i*MLP_;
        const __half* W2 = w2t + (long long)i*D_*MLP_; const float* B2 = b2 + (long long)i*D_;

        ln_kernel<<<(MTOK*32+255)/256, 256>>>(x, h, ln1_g + (long long)i*D_, ln1_b + (long long)i*D_, MTOK);

        // fused QKV: qkv[6304 x 2304] = h @ Wqkv^T + b (plain coalesced epilogue)
        tgemm<128,128,0,true><<<dim3(18,50,1), 256, SM128>>>(h, Wqkv, Bqkv, nullptr,
            qkv, MTOK, 3*D_, D_, D_, D_, 2304, 1, 0,0, 0,0, 0,0);

        // per-head V transpose (coalesced both ways)
        vtrans_kernel<<<dim3(2,7,B_*HEADS_), tb>>>(qkv, vt);

        // S = softmax(Q K^T / 8) per (b,h): BM=64 tile, KT=1, 1-stage smem
        tgemm<64,256,5,false><<<dim3(1,4,B_*HEADS_), 256, SMQK>>>(qkv, qkv + 768, nullptr, nullptr,
            sc, N_, N_, DH_, 2304, 2304, NPAD, HEADS_,
            sQb, sQh, sQb, sQh, sSb, sSh);

        // O = P @ V per (b,h): [197 x 64], K=256 (zero-padded)
        tgemm<128,64,0,true><<<dim3(1,2,B_*HEADS_), 256, SM64>>>(sc, vt, nullptr, nullptr,
            o, N_, DH_, NPAD, NPAD, NPAD, D_, HEADS_,
            sSb, sSh, sVb, sVh, sOb, sOh);

        // x = x + O @ Wo^T + bo  (fp32 residual out)
        tgemm<128,128,2,false><<<dim3(6,50,1), 256, SM128>>>(o, Wo, Bo, x,
            x, MTOK, D_, D_, D_, D_, D_, 1, 0,0, 0,0, 0,0);

        ln_kernel<<<(MTOK*32+255)/256, 256>>>(x, h, ln2_g + (long long)i*D_, ln2_b + (long long)i*D_, MTOK);

        tgemm<128,128,1,true><<<dim3(24,50,1), 256, SM128>>>(h, W1, B1, nullptr,
            mlp, MTOK, MLP_, D_, D_, D_, MLP_, 1, 0,0, 0,0, 0,0);
        tgemm<128,128,2,false><<<dim3(6,50,1), 256, SM128>>>(mlp, W2, B2, x,
            x, MTOK, D_, MLP_, MLP_, MLP_, D_, 1, 0,0, 0,0, 0,0);
    }

    pool_kernel<<<B_, 256>>>(x, pool);
    ln_kernel<<<(B_*32+255)/256, 256>>>(pool, pln, hn_g, hn_b, B_);
    tgemm<128,128,0,false><<<dim3(8,1,1), 256, SM128>>>(pln, hwt, hb, nullptr,
        outp, B_, NC_, D_, D_, D_, NC_, 1, 0,0, 0,0, 0,0);
}

// round 16
// speedup vs baseline: 1.0215x; 1.0073x over previous
#include <cuda_runtime.h>
#include <cuda_fp16.h>
#include <cstdint>
#include <math.h>

#define B_ 32
#define D_ 768
#define L_ 12
#define HEADS_ 12
#define DH_ 64
#define MLP_ 3072
#define NC_ 1000
#define N_ 197
#define NP_ 196
#define NPAD 256
#define MTOK (B_*N_)       // 6304
#define MPATCH (B_*NP_)    // 6272

// ---------------- scratch (device globals; no runtime allocation) ----------
__device__ float  g_x  [MTOK*D_];                         // residual stream fp32
__device__ __half g_h  [MTOK*D_];
__device__ __half g_qkv[(long long)MTOK*3*D_];            // fused q|k|v, ld=2304
__device__ __half g_o  [MTOK*D_];
__device__ __half g_mlp[(long long)MTOK*MLP_];
__device__ __half g_sc [(long long)B_*HEADS_*N_*NPAD];    // probs, ld=256
__device__ __half g_vt [(long long)B_*HEADS_*DH_*NPAD];   // V^T per head, ld=256
__device__ __half g_col[(long long)MPATCH*768];
__device__ float  g_po [(long long)MPATCH*D_];
__device__ float  g_pool[B_*D_];
__device__ __half g_pln [B_*D_];
__device__ __half g_pwr[(long long)D_*768];               // patch_w as half
// transposed (half) weights, [N,K] K-major
__device__ __half g_wqkvt[(long long)L_*3*D_*D_];         // stacked q|k|v, 2304 x 768
__device__ float  g_bqkv [(long long)L_*3*D_];            // stacked biases (fp32)
__device__ __half g_wot[(long long)L_*D_*D_];
__device__ __half g_w1t[(long long)L_*D_*MLP_];
__device__ __half g_w2t[(long long)L_*D_*MLP_];
__device__ __half g_hwt[(long long)NC_*D_];

__device__ __forceinline__ float gelu_f(float x) {
    float x3 = x*x*x;
    return 0.5f*x*(1.0f + tanhf(0.7978845608028654f*(x + 0.044715f*x3)));
}

// ---------------- PTX helpers ----------------------------------------------
__device__ __forceinline__ uint32_t smem_u32(const void* p){
    uint32_t a;
    asm("{ .reg .u64 t; cvta.to.shared.u64 t, %1; cvt.u32.u64 %0, t; }" : "=r"(a) : "l"(p));
    return a;
}
__device__ __forceinline__ void cp16(uint32_t dst, const void* src, int srcbytes){
    asm volatile("cp.async.cg.shared.global [%0], [%1], 16, %2;"
                 :: "r"(dst), "l"(src), "r"(srcbytes));
}
#define CP_COMMIT() asm volatile("cp.async.commit_group;" ::: "memory")
template<int Nw> __device__ __forceinline__ void cp_wait(){
    asm volatile("cp.async.wait_group %0;" :: "n"(Nw) : "memory");
}
// fp16 mma: D += A*B, m16n8k16, fp32 accumulate
__device__ __forceinline__ void mma16(float* d, const uint32_t* a, uint32_t b0, uint32_t b1){
    asm volatile("mma.sync.aligned.m16n8k16.row.col.f32.f16.f16.f32 "
        "{%0,%1,%2,%3}, {%4,%5,%6,%7}, {%8,%9}, {%0,%1,%2,%3};"
        : "+f"(d[0]), "+f"(d[1]), "+f"(d[2]), "+f"(d[3])
        : "r"(a[0]), "r"(a[1]), "r"(a[2]), "r"(a[3]), "r"(b0), "r"(b1));
}
__device__ __forceinline__ void ldsm4(uint32_t& r0, uint32_t& r1, uint32_t& r2, uint32_t& r3,
                                      uint32_t addr){
    asm volatile("ldmatrix.sync.aligned.m8n8.x4.shared.b16 {%0,%1,%2,%3}, [%4];"
        : "=r"(r0), "=r"(r1), "=r"(r2), "=r"(r3) : "r"(addr));
}
#define SWZ128(o) ((o) ^ (((o) >> 3) & 0x70))

// ---------------- mma.sync fp16 batched GEMM --------------------------------
// C[M,N] = A[M,K] @ B[N,K]^T  (both half, K-major). K must be a multiple of 64.
// BK = 64 halves = one 128B SW128 atom per row. Fragments loaded via
// ldmatrix.x4 with per-lane swizzle constant lx; A and B consume the identical
// chunk permutation (ks, ks+4) -> exact. Register ping-pong on fragments.
// BM in {64,128}: warp grid is (BM/32) x (8/(BM/32)).
// EPI: 0 bias, 1 bias+gelu, 2 bias+residual(float out),
//      5 fused softmax (scores -> probs half, scale 0.125, valid cols < 197)
// RND=true: output is __half; RND=false: output is float (EPI 5 always half).
template<int BM, int BN, int EPI, bool RND>
__global__ void __launch_bounds__(256, 2)
tgemm(const __half* __restrict__ A, const __half* __restrict__ Bm,
      const float* __restrict__ bias, const float* __restrict__ Res,
      void* __restrict__ C,
      int M, int Nn, int K, int lda, int ldb, int ldc, int zdiv,
      long long sA1, long long sA2, long long sB1, long long sB2,
      long long sC1, long long sC2)
{
    constexpr int BK = 64, S = 3;
    constexpr int ABYT = BM * 128;                 // bytes per A stage
    constexpr int BBYT = BN * 128;
    constexpr int STGB = ABYT + BBYT;
    constexpr int WROWS = BM / 32;                 // warps along M
    constexpr int WCOLS = 8 / WROWS;               // warps along N
    constexpr int WN  = BN / WCOLS;                // warp tile N
    constexpr int NT  = WN / 8;
    constexpr int NP2 = NT / 2;

    extern __shared__ float smf[];
    uint32_t sb = smem_u32(smf);
    int tid = threadIdx.x, lane = tid & 31, wid = tid >> 5;
    int wm = wid % WROWS, wn = wid / WROWS;

    int rowBase = blockIdx.y * BM;
    int colBase = blockIdx.x * BN;
    int zb = blockIdx.z / zdiv, zh = blockIdx.z - zb * zdiv;
    const __half* Ab = A  + zb * sA1 + zh * sA2;
    const __half* Bb = Bm + zb * sB1 + zh * sB2;
    long long zco = zb * sC1 + zh * sC2;
    float*  Cf = (float*)C + zco;
    __half* Ch = (__half*)C + zco;
    const float* Rb = (EPI == 2) ? (Res + zco) : nullptr;

    const int KT = K / BK;

    auto load_tile = [&](int kt, int st){
        int k0 = kt * BK;
        uint32_t abase = sb + (uint32_t)(st * STGB);
        uint32_t bbase = abase + (uint32_t)ABYT;
        #pragma unroll
        for (int i = 0; i < BM*8/256; i++){
            int c = tid + i*256;
            int r = c >> 3, kc = c & 7;
            int gr = rowBase + r;
            const __half* src = Ab + (long long)min(gr, M-1) * lda + k0 + kc*8;
            cp16(abase + SWZ128(r*128 + kc*16), src, (gr < M) ? 16 : 0);
        }
        #pragma unroll
        for (int i = 0; i < BN*8/256; i++){
            int c = tid + i*256;
            int r = c >> 3, kc = c & 7;
            int gn = colBase + r;
            const __half* src = Bb + (long long)min(gn, Nn-1) * ldb + k0 + kc*8;
            cp16(bbase + SWZ128(r*128 + kc*16), src, (gn < Nn) ? 16 : 0);
        }
        CP_COMMIT();
    };

    float acc[2][NT][4];
    #pragma unroll
    for (int mt = 0; mt < 2; mt++)
        #pragma unroll
        for (int nt = 0; nt < NT; nt++)
            #pragma unroll
            for (int j = 0; j < 4; j++) acc[mt][nt][j] = 0.0f;

    int pf = (S-1 < KT) ? S-1 : KT;
    for (int t = 0; t < pf; t++) load_tile(t, t % S);

    int rfrag = lane >> 2, cfrag = lane & 3;
    // ldmatrix per-lane constants
    int lane15 = lane & 15;
    uint32_t lx = (uint32_t)(((lane >> 4) << 2) ^ (lane & 7));   // chunk-xor constant
    uint32_t aRowOff = (uint32_t)(wm*32 + lane15) * 128u;        // + mt*2048
    uint32_t bRowOff = (uint32_t)(wn*WN + lane15) * 128u;        // + p*2048

    uint32_t afr[2][2][4];        // [buf][mt][4]
    uint32_t bfr[2][NP2][4];      // [buf][p][4]

    auto load_frags = [&](uint32_t aAddr, uint32_t bAddr, int ks, int buf){
        uint32_t koff = (uint32_t)((ks ^ (int)lx) << 4);
        #pragma unroll
        for (int mt = 0; mt < 2; mt++)
            ldsm4(afr[buf][mt][0], afr[buf][mt][1], afr[buf][mt][2], afr[buf][mt][3],
                  aAddr + mt*2048u + koff);
        #pragma unroll
        for (int p = 0; p < NP2; p++)
            ldsm4(bfr[buf][p][0], bfr[buf][p][1], bfr[buf][p][2], bfr[buf][p][3],
                  bAddr + p*2048u + koff);
    };

    for (int kt = 0; kt < KT; kt++){
        if (kt == KT-1) cp_wait<0>(); else cp_wait<S-2>();
        __syncthreads();
        if (kt + S - 1 < KT) load_tile(kt + S - 1, (kt + S - 1) % S);

        uint32_t abase = sb + (uint32_t)((kt % S) * STGB);
        uint32_t bbase = abase + (uint32_t)ABYT;
        uint32_t aAddr = abase + aRowOff;
        uint32_t bAddr = bbase + bRowOff;
        load_frags(aAddr, bAddr, 0, 0);
        #pragma unroll
        for (int ks = 0; ks < 4; ks++){
            int cur = ks & 1;
            if (ks < 3) load_frags(aAddr, bAddr, ks+1, cur ^ 1);
            #pragma unroll
            for (int p = 0; p < NP2; p++){
                mma16(acc[0][2*p],   afr[cur][0], bfr[cur][p][0], bfr[cur][p][2]);
                mma16(acc[1][2*p],   afr[cur][1], bfr[cur][p][0], bfr[cur][p][2]);
                mma16(acc[0][2*p+1], afr[cur][0], bfr[cur][p][1], bfr[cur][p][3]);
                mma16(acc[1][2*p+1], afr[cur][1], bfr[cur][p][1], bfr[cur][p][3]);
            }
        }
    }

    if (EPI == 5){
        // ---- fused softmax epilogue: rows over cols [0, 197) ----
        __syncthreads();                       // smem reuse safety
        float* redm = smf;                     // [WCOLS][BM]
        float* reds = smf + WCOLS*BM;          // [WCOLS][BM]
        #pragma unroll
        for (int mt = 0; mt < 2; mt++)
            #pragma unroll
            for (int nt = 0; nt < NT; nt++)
                #pragma unroll
                for (int j = 0; j < 4; j++){
                    int gc = colBase + wn*WN + nt*8 + cfrag*2 + (j & 1);
                    acc[mt][nt][j] = (gc < N_) ? acc[mt][nt][j] * 0.125f : -1e30f;
                }
        float rmax[2][2];
        #pragma unroll
        for (int mt = 0; mt < 2; mt++)
            #pragma unroll
            for (int jr = 0; jr < 2; jr++){
                float m = -1e30f;
                #pragma unroll
                for (int nt = 0; nt < NT; nt++)
                    m = fmaxf(m, fmaxf(acc[mt][nt][jr*2], acc[mt][nt][jr*2+1]));
                m = fmaxf(m, __shfl_xor_sync(0xffffffffu, m, 1));
                m = fmaxf(m, __shfl_xor_sync(0xffffffffu, m, 2));
                rmax[mt][jr] = m;
            }
        if (cfrag == 0){
            #pragma unroll
            for (int mt = 0; mt < 2; mt++)
                #pragma unroll
                for (int jr = 0; jr < 2; jr++)
                    redm[wn*BM + wm*32 + mt*16 + jr*8 + rfrag] = rmax[mt][jr];
        }
        __syncthreads();
        float gmax[2][2], rsum[2][2];
        #pragma unroll
        for (int mt = 0; mt < 2; mt++)
            #pragma unroll
            for (int jr = 0; jr < 2; jr++){
                int rl = wm*32 + mt*16 + jr*8 + rfrag;
                float m = -1e30f;
                #pragma unroll
                for (int c = 0; c < WCOLS; c++)
                    m = fmaxf(m, redm[c*BM + rl]);
                gmax[mt][jr] = m;
                rsum[mt][jr] = 0.0f;
            }
        #pragma unroll
        for (int mt = 0; mt < 2; mt++)
            #pragma unroll
            for (int nt = 0; nt < NT; nt++)
                #pragma unroll
                for (int j = 0; j < 4; j++){
                    int gc = colBase + wn*WN + nt*8 + cfrag*2 + (j & 1);
                    float e = (gc < N_) ? __expf(acc[mt][nt][j] - gmax[mt][j>>1]) : 0.0f;
                    acc[mt][nt][j] = e;
                    rsum[mt][j>>1] += e;
                }
        #pragma unroll
        for (int mt = 0; mt < 2; mt++)
            #pragma unroll
            for (int jr = 0; jr < 2; jr++){
                float s = rsum[mt][jr];
                s += __shfl_xor_sync(0xffffffffu, s, 1);
                s += __shfl_xor_sync(0xffffffffu, s, 2);
                rsum[mt][jr] = s;
            }
        if (cfrag == 0){
            #pragma unroll
            for (int mt = 0; mt < 2; mt++)
                #pragma unroll
                for (int jr = 0; jr < 2; jr++)
                    reds[wn*BM + wm*32 + mt*16 + jr*8 + rfrag] = rsum[mt][jr];
        }
        __syncthreads();
        #pragma unroll
        for (int mt = 0; mt < 2; mt++)
            #pragma unroll
            for (int jr = 0; jr < 2; jr++){
                int rl = wm*32 + mt*16 + jr*8 + rfrag;
                int gr = rowBase + rl;
                if (gr >= M) continue;
                float ssum = 0.0f;
                #pragma unroll
                for (int c = 0; c < WCOLS; c++) ssum += reds[c*BM + rl];
                float inv = 1.0f / ssum;
                #pragma unroll
                for (int nt = 0; nt < NT; nt++){
                    int gc0 = colBase + wn*WN + nt*8 + cfrag*2;
                    if (gc0 >= NPAD) continue;
                    *(__half2*)(Ch + (long long)gr * ldc + gc0) =
                        __floats2half2_rn(acc[mt][nt][jr*2+0] * inv,
                                          acc[mt][nt][jr*2+1] * inv);
                }
            }
    } else {
        // ---- generic vectorized epilogue ----
        #pragma unroll
        for (int mt = 0; mt < 2; mt++){
            #pragma unroll
            for (int jr = 0; jr < 2; jr++){
                int gr = rowBase + wm*32 + mt*16 + jr*8 + rfrag;
                if (gr >= M) continue;
                #pragma unroll
                for (int nt = 0; nt < NT; nt++){
                    int gc = colBase + wn*WN + nt*8 + cfrag*2;
                    if (gc >= Nn) continue;
                    float v0 = acc[mt][nt][jr*2+0];
                    float v1 = acc[mt][nt][jr*2+1];
                    if (bias){
                        float2 b2 = *(const float2*)(bias + gc);
                        v0 += b2.x; v1 += b2.y;
                    }
                    if (EPI == 1){ v0 = gelu_f(v0); v1 = gelu_f(v1); }
                    if (EPI == 2){
                        float2 r2 = *(const float2*)(Rb + (long long)gr * ldc + gc);
                        v0 += r2.x; v1 += r2.y;
                    }
                    if (RND){
                        *(__half2*)(Ch + (long long)gr * ldc + gc) = __floats2half2_rn(v0, v1);
                    } else {
                        *(float2*)(Cf + (long long)gr * ldc + gc) = make_float2(v0, v1);
                    }
                }
            }
        }
    }
}

// ---------------- per-head V transpose: vt[bh][d][n] = qkv[b,n][1536+h*64+d] -
__global__ void vtrans_kernel(const __half* __restrict__ qkv, __half* __restrict__ vt){
    __shared__ __half t[32][33];
    int bh = blockIdx.z;
    int b = bh / HEADS_, h = bh % HEADS_;
    const __half* ip = qkv + ((long long)b * N_) * 2304 + 1536 + h * DH_;
    __half* op = vt + ((long long)bh * DH_) * NPAD;
    int d0 = blockIdx.x * 32, n0 = blockIdx.y * 32;
    int x = threadIdx.x, y = threadIdx.y;
    #pragma unroll
    for (int i = 0; i < 32; i += 8){
        int n = n0 + y + i, d = d0 + x;
        if (n < N_ && d < DH_) t[y+i][x] = ip[(long long)n * 2304 + d];
    }
    __syncthreads();
    #pragma unroll
    for (int i = 0; i < 32; i += 8){
        int d = d0 + y + i, n = n0 + x;
        if (d < DH_ && n < N_) op[(long long)d * NPAD + n] = t[x][y+i];
    }
}

// ---------------- weight transpose fp32 -> half (with row offset) ----------
__global__ void transpose_kernel(const float* __restrict__ in, __half* __restrict__ out,
                                 int R, int C, int ldo, int rowOff,
                                 long long inb, long long outb){
    __shared__ float t[32][33];
    const float* ip = in + blockIdx.z * inb;
    __half* op = out + blockIdx.z * outb;
    int c0 = blockIdx.x * 32, r0 = blockIdx.y * 32;
    int x = threadIdx.x, y = threadIdx.y;
    #pragma unroll
    for (int i = 0; i < 32; i += 8){
        int r = r0 + y + i, c = c0 + x;
        if (r < R && c < C) t[y+i][x] = ip[(long long)r*C + c];
    }
    __syncthreads();
    #pragma unroll
    for (int i = 0; i < 32; i += 8){
        int r = c0 + y + i, c = r0 + x;
        if (r < C && c < R) op[(long long)(rowOff + r)*ldo + c] = __float2half_rn(t[x][y+i]);
    }
}

// ---------------- misc small kernels ---------------------------------------
__global__ void zeroh_kernel(__half* __restrict__ p, long long n){
    long long stride = (long long)gridDim.x * blockDim.x;
    for (long long i = (long long)blockIdx.x * blockDim.x + threadIdx.x; i < n; i += stride)
        p[i] = __float2half_rn(0.0f);
}
__global__ void tohalf_kernel(const float* __restrict__ in, __half* __restrict__ out, long long n){
    long long stride = (long long)gridDim.x * blockDim.x;
    for (long long i = (long long)blockIdx.x * blockDim.x + threadIdx.x; i < n; i += stride)
        out[i] = __float2half_rn(in[i]);
}
__global__ void stackb_kernel(const float* __restrict__ bq, const float* __restrict__ bk,
                              const float* __restrict__ bv, float* __restrict__ out){
    int i = blockIdx.x * blockDim.x + threadIdx.x;
    if (i >= L_ * 3 * D_) return;
    int l = i / (3*D_), j = i % (3*D_);
    float v = (j < D_) ? bq[l*D_ + j] : (j < 2*D_) ? bk[l*D_ + j - D_] : bv[l*D_ + j - 2*D_];
    out[i] = v;
}

// ---------------- im2col for 16x16 stride-16 patches -> half ---------------
__global__ void im2col_kernel(const float* __restrict__ img, __half* __restrict__ out) {
    long long total = (long long)MPATCH * 768;
    long long stride = (long long)gridDim.x * blockDim.x;
    for (long long idx = (long long)blockIdx.x * blockDim.x + threadIdx.x; idx < total; idx += stride) {
        int kk = (int)(idx % 768);
        long long row = idx / 768;
        int b = (int)(row / NP_);
        int p = (int)(row % NP_);
        int ph = p / 14, pw = p % 14;
        int c = kk >> 8;
        int rem = kk & 255;
        int i = rem >> 4, j = rem & 15;
        out[idx] = __float2half_rn(img[(((long long)b*3 + c)*224 + (ph*16 + i))*224 + (pw*16 + j)]);
    }
}

// ---------------- cls + patches + pos_emb assemble (fp32 residual init) ----
__global__ void assemble_kernel(const float* __restrict__ po, const float* __restrict__ cls,
                                const float* __restrict__ pos, float* __restrict__ x) {
    long long total = (long long)MTOK * D_;
    long long stride = (long long)gridDim.x * blockDim.x;
    for (long long idx = (long long)blockIdx.x * blockDim.x + threadIdx.x; idx < total; idx += stride) {
        int d = (int)(idx % D_);
        long long row = idx / D_;
        int b = (int)(row / N_);
        int n = (int)(row % N_);
        float v = (n == 0) ? cls[d] : po[((long long)b*NP_ + (n-1))*D_ + d];
        x[idx] = v + pos[(long long)n*D_ + d];
    }
}

// ---------------- LayerNorm: warp per row of 768, fp32 in -> half out ------
__global__ void ln_kernel(const float* __restrict__ in, __half* __restrict__ out,
                          const float* __restrict__ g, const float* __restrict__ bb, int rows) {
    int w = (blockIdx.x * blockDim.x + threadIdx.x) >> 5;
    int lane = threadIdx.x & 31;
    if (w >= rows) return;
    const float4* ip = (const float4*)(in + (long long)w * D_);
    float4 vv[6];
    float s = 0.f, q = 0.f;
    #pragma unroll
    for (int j = 0; j < 6; j++){
        vv[j] = ip[lane + j*32];
        s += vv[j].x + vv[j].y + vv[j].z + vv[j].w;
        q += vv[j].x*vv[j].x + vv[j].y*vv[j].y + vv[j].z*vv[j].z + vv[j].w*vv[j].w;
    }
    #pragma unroll
    for (int o = 16; o; o >>= 1){
        s += __shfl_xor_sync(0xffffffffu, s, o);
        q += __shfl_xor_sync(0xffffffffu, q, o);
    }
    float mu = s * (1.0f/D_);
    float rs = rsqrtf(q * (1.0f/D_) - mu*mu + 1e-5f);
    __half2* op = (__half2*)(out + (long long)w * D_);
    const float4* gp = (const float4*)g;
    const float4* bp = (const float4*)bb;
    #pragma unroll
    for (int j = 0; j < 6; j++){
        int i = lane + j*32;
        float4 gg = gp[i], b2 = bp[i], v = vv[j];
        op[2*i]   = __floats2half2_rn((v.x-mu)*rs*gg.x + b2.x, (v.y-mu)*rs*gg.y + b2.y);
        op[2*i+1] = __floats2half2_rn((v.z-mu)*rs*gg.z + b2.z, (v.w-mu)*rs*gg.w + b2.w);
    }
}

// ---------------- mean pool over tokens ------------------------------------
__global__ void pool_kernel(const float* __restrict__ x, float* __restrict__ out) {
    int b = blockIdx.x;
    for (int d = threadIdx.x; d < D_; d += blockDim.x) {
        float s = 0.0f;
        const float* p = x + ((long long)b * N_) * D_ + d;
        for (int n = 0; n < N_; n++) s += p[(long long)n * D_];
        out[b*D_ + d] = s * (1.0f / N_);
    }
}

// ---------------- launcher --------------------------------------------------
extern "C" void kernel_launch(void* const* d_in, const int* in_sizes, int n_in,
                              void* d_out, int out_size) {
    const float* imgs    = (const float*)d_in[0];
    const float* patch_w = (const float*)d_in[1];
    const float* patch_b = (const float*)d_in[2];
    const float* cls_tok = (const float*)d_in[3];
    const float* pos_emb = (const float*)d_in[4];
    const float* ln1_g   = (const float*)d_in[5];
    const float* ln1_b   = (const float*)d_in[6];
    const float* wq      = (const float*)d_in[7];
    const float* bq      = (const float*)d_in[8];
    const float* wk      = (const float*)d_in[9];
    const float* bk      = (const float*)d_in[10];
    const float* wv      = (const float*)d_in[11];
    const float* bv      = (const float*)d_in[12];
    const float* wo      = (const float*)d_in[13];
    const float* bo      = (const float*)d_in[14];
    const float* ln2_g   = (const float*)d_in[15];
    const float* ln2_b   = (const float*)d_in[16];
    const float* w1      = (const float*)d_in[17];
    const float* b1      = (const float*)d_in[18];
    const float* w2      = (const float*)d_in[19];
    const float* b2      = (const float*)d_in[20];
    const float* hn_g    = (const float*)d_in[21];
    const float* hn_b    = (const float*)d_in[22];
    const float* hw      = (const float*)d_in[23];
    const float* hb      = (const float*)d_in[24];
    float* outp = (float*)d_out;

    float *x,*po,*pool; float *bqkv;
    __half *h,*qkv,*o,*mlp,*sc,*vt,*col,*pln,*pwr;
    __half *wqkvt,*wot,*w1t,*w2t,*hwt;
    cudaGetSymbolAddress((void**)&x,    g_x);
    cudaGetSymbolAddress((void**)&h,    g_h);
    cudaGetSymbolAddress((void**)&qkv,  g_qkv);
    cudaGetSymbolAddress((void**)&o,    g_o);
    cudaGetSymbolAddress((void**)&mlp,  g_mlp);
    cudaGetSymbolAddress((void**)&sc,   g_sc);
    cudaGetSymbolAddress((void**)&vt,   g_vt);
    cudaGetSymbolAddress((void**)&col,  g_col);
    cudaGetSymbolAddress((void**)&po,   g_po);
    cudaGetSymbolAddress((void**)&pool, g_pool);
    cudaGetSymbolAddress((void**)&pln,  g_pln);
    cudaGetSymbolAddress((void**)&pwr,  g_pwr);
    cudaGetSymbolAddress((void**)&wqkvt,g_wqkvt);
    cudaGetSymbolAddress((void**)&bqkv, g_bqkv);
    cudaGetSymbolAddress((void**)&wot,  g_wot);
    cudaGetSymbolAddress((void**)&w1t,  g_w1t);
    cudaGetSymbolAddress((void**)&w2t,  g_w2t);
    cudaGetSymbolAddress((void**)&hwt,  g_hwt);

    const int SM128 = 3 * (128 + 128) * 128;   // 98304 B
    const int SMQK  = (64 + 256) * 128;        // 40960 B
    const int SM64  = 3 * (128 +  64) * 128;   // 73728 B
    cudaFuncSetAttribute((const void*)tgemm<128,128,0,false>, cudaFuncAttributeMaxDynamicSharedMemorySize, SM128);
    cudaFuncSetAttribute((const void*)tgemm<128,128,0,true>,  cudaFuncAttributeMaxDynamicSharedMemorySize, SM128);
    cudaFuncSetAttribute((const void*)tgemm<64,256,5,false>,  cudaFuncAttributeMaxDynamicSharedMemorySize, SMQK);
    cudaFuncSetAttribute((const void*)tgemm<128,64,0,true>,   cudaFuncAttributeMaxDynamicSharedMemorySize, SM64);
    cudaFuncSetAttribute((const void*)tgemm<128,128,2,false>, cudaFuncAttributeMaxDynamicSharedMemorySize, SM128);
    cudaFuncSetAttribute((const void*)tgemm<128,128,1,true>,  cudaFuncAttributeMaxDynamicSharedMemorySize, SM128);

    // side stream + events (created per call; intentionally not destroyed —
    // destroying capture-participating streams/events would invalidate the graph;
    // kernel_launch runs only twice, host-side leak is bounded and legal)
    cudaStream_t s1;
    cudaStreamCreateWithFlags(&s1, cudaStreamNonBlocking);
    cudaEvent_t evRoot, evPwr, evPre, evQ[L_], evS[L_];
    cudaEventCreateWithFlags(&evRoot, cudaEventDisableTiming);
    cudaEventCreateWithFlags(&evPwr,  cudaEventDisableTiming);
    cudaEventCreateWithFlags(&evPre,  cudaEventDisableTiming);
    for (int i = 0; i < L_; i++){
        cudaEventCreateWithFlags(&evQ[i], cudaEventDisableTiming);
        cudaEventCreateWithFlags(&evS[i], cudaEventDisableTiming);
    }

    dim3 tb(32,8);
    // fork: s1 handles all weight prep; stream 0 handles the patch-embed chain
    cudaEventRecord(evRoot, 0);
    cudaStreamWaitEvent(s1, evRoot, 0);

    tohalf_kernel<<<1024, 256, 0, s1>>>(patch_w, pwr, (long long)D_*768);
    cudaEventRecord(evPwr, s1);
    transpose_kernel<<<dim3(24,24,L_), tb, 0, s1>>>(wq, wqkvt, D_, D_, D_, 0,     (long long)D_*D_, (long long)3*D_*D_);
    transpose_kernel<<<dim3(24,24,L_), tb, 0, s1>>>(wk, wqkvt, D_, D_, D_, D_,    (long long)D_*D_, (long long)3*D_*D_);
    transpose_kernel<<<dim3(24,24,L_), tb, 0, s1>>>(wv, wqkvt, D_, D_, D_, 2*D_,  (long long)D_*D_, (long long)3*D_*D_);
    transpose_kernel<<<dim3(24,24,L_), tb, 0, s1>>>(wo, wot,   D_, D_, D_, 0,     (long long)D_*D_, (long long)D_*D_);
    transpose_kernel<<<dim3(96,24,L_), tb, 0, s1>>>(w1, w1t,   D_, MLP_, D_, 0,   (long long)D_*MLP_, (long long)D_*MLP_);
    transpose_kernel<<<dim3(24,96,L_), tb, 0, s1>>>(w2, w2t,   MLP_, D_, MLP_, 0, (long long)D_*MLP_, (long long)D_*MLP_);
    transpose_kernel<<<dim3(32,24,1),  tb, 0, s1>>>(hw, hwt, D_, NC_, D_, 0, 0, 0);
    stackb_kernel<<<(L_*3*D_ + 255)/256, 256, 0, s1>>>(bq, bk, bv, bqkv);
    zeroh_kernel<<<1024, 256, 0, s1>>>(vt, (long long)B_*HEADS_*DH_*NPAD);
    cudaEventRecord(evPre, s1);

    im2col_kernel<<<4096, 256>>>(imgs, col);
    cudaStreamWaitEvent(0, evPwr, 0);   // patch GEMM needs pwr from s1
    tgemm<128,128,0,false><<<dim3(6,49,1), 256, SM128>>>(col, pwr, patch_b, nullptr,
        po, MPATCH, D_, 768, 768, 768, 768, 1, 0,0, 0,0, 0,0);
    assemble_kernel<<<4096, 256>>>(po, cls_tok, pos_emb, x);
    cudaStreamWaitEvent(0, evPre, 0);   // weights + vt-zero ready before layers

    const long long sQb = (long long)N_*2304, sQh = DH_;
    const long long sSb = (long long)HEADS_*N_*NPAD, sSh = (long long)N_*NPAD;
    const long long sVb = (long long)HEADS_*DH_*NPAD, sVh = (long long)DH_*NPAD;
    const long long sOb = (long long)N_*D_, sOh = DH_;

    for (int i = 0; i < L_; i++) {
        const __half* Wqkv = wqkvt + (long long)i*3*D_*D_;
        const float*  Bqkv = bqkv  + (long long)i*3*D_;
        const __half* Wo = wot + (long long)i*D_*D_;   const float* Bo = bo + (long long)i*D_;
        const __half* W1 = w1t + (long long)i*D_*MLP_; const float* B1 = b1 + (long long)i*MLP_;
        const __half* W2 = w2t + (long long)i*D_*MLP_; const float* B2 = b2 + (long long)i*D_;

        ln_kernel<<<(MTOK*32+255)/256, 256>>>(x, h, ln1_g + (long long)i*D_, ln1_b + (long long)i*D_, MTOK);

        // fused QKV: qkv[6304 x 2304] = h @ Wqkv^T + b
        tgemm<128,128,0,true><<<dim3(18,50,1), 256, SM128>>>(h, Wqkv, Bqkv, nullptr,
            qkv, MTOK, 3*D_, D_, D_, D_, 2304, 1, 0,0, 0,0, 0,0);
        cudaEventRecord(evQ[i], 0);

        // QK-softmax on side stream, vtrans on main stream (both read qkv only)
        cudaStreamWaitEvent(s1, evQ[i], 0);
        tgemm<64,256,5,false><<<dim3(1,4,B_*HEADS_), 256, SMQK, s1>>>(qkv, qkv + 768, nullptr, nullptr,
            sc, N_, N_, DH_, 2304, 2304, NPAD, HEADS_,
            sQb, sQh, sQb, sQh, sSb, sSh);
        cudaEventRecord(evS[i], s1);

        vtrans_kernel<<<dim3(2,7,B_*HEADS_), tb>>>(qkv, vt);
        cudaStreamWaitEvent(0, evS[i], 0);  // PV needs probs from s1

        // O = P @ V per (b,h): [197 x 64], K=256 (zero-padded)
        tgemm<128,64,0,true><<<dim3(1,2,B_*HEADS_), 256, SM64>>>(sc, vt, nullptr, nullptr,
            o, N_, DH_, NPAD, NPAD, NPAD, D_, HEADS_,
            sSb, sSh, sVb, sVh, sOb, sOh);

        // x = x + O @ Wo^T + bo  (fp32 residual out)
        tgemm<128,128,2,false><<<dim3(6,50,1), 256, SM128>>>(o, Wo, Bo, x,
            x, MTOK, D_, D_, D_, D_, D_, 1, 0,0, 0,0, 0,0);

        ln_kernel<<<(MTOK*32+255)/256, 256>>>(x, h, ln2_g + (long long)i*D_, ln2_b + (long long)i*D_, MTOK);

        tgemm<128,128,1,true><<<dim3(24,50,1), 256, SM128>>>(h, W1, B1, nullptr,
            mlp, MTOK, MLP_, D_, D_, D_, MLP_, 1, 0,0, 0,0, 0,0);
        tgemm<128,128,2,false><<<dim3(6,50,1), 256, SM128>>>(mlp, W2, B2, x,
            x, MTOK, D_, MLP_, MLP_, MLP_, D_, 1, 0,0, 0,0, 0,0);
    }

    pool_kernel<<<B_, 256>>>(x, pool);
    ln_kernel<<<(B_*32+255)/256, 256>>>(pool, pln, hn_g, hn_b, B_);
    tgemm<128,128,0,false><<<dim3(8,1,1), 256, SM128>>>(pln, hwt, hb, nullptr,
        outp, B_, NC_, D_, D_, D_, NC_, 1, 0,0, 0,0, 0,0);
}